// round 7
// baseline (speedup 1.0000x reference)
#include <cuda_runtime.h>
#include <cuda_fp16.h>
#include <cstdint>

#define B_ 256
#define I_ 1152
#define N_ 10
#define D_ 16
#define K_ 8

// u_hat scratch, layout [b][n][i][d], fp16 = 94 MB
__device__ __half g_uhat[(size_t)B_ * N_ * I_ * D_];

// ---------------- helpers ----------------
__device__ __forceinline__ unsigned long long pack2(float a, float b) {
    unsigned long long r;
    asm("mov.b64 %0, {%1, %2};" : "=l"(r) : "f"(a), "f"(b));
    return r;
}
__device__ __forceinline__ unsigned long long fma2(unsigned long long a,
                                                   unsigned long long b,
                                                   unsigned long long c) {
    unsigned long long r;
    asm("fma.rn.f32x2 %0, %1, %2, %3;" : "=l"(r) : "l"(a), "l"(b), "l"(c));
    return r;
}
__device__ __forceinline__ unsigned int cvt2h(unsigned long long v) {
    float lo, hi;
    asm("mov.b64 {%0, %1}, %2;" : "=f"(lo), "=f"(hi) : "l"(v));
    __half2 h = __floats2half2_rn(lo, hi);
    return *reinterpret_cast<unsigned int*>(&h);
}

// ---------------- kernel 1: u_hat = einsum('nidk,bik->bnid') fp16 -------------
// Grid 576 = 144 i-groups x 4 b-quarters. 320 threads = (iloc 8) x (n 10) x (dq 4).
// x staged in smem duplicated as (x,x) u64 -> hot-loop LDS.64 is warp-broadcast.
// W held in registers (16 u64 of d-paired values).
__global__ __launch_bounds__(320, 2) void k_uhat(const float* __restrict__ x,
                                                 const float* __restrict__ W) {
    __shared__ unsigned long long sx[64 * 64];  // [bl][il*8+k], 32 KB
    const int tid = threadIdx.x;
    const int ig = blockIdx.x >> 2;
    const int bq = blockIdx.x & 3;
    const int i0 = ig * 8;
    const int b0 = bq * 64;

    // stage x (fully coalesced reads), duplicate each float into u64 lanes
    for (int t = tid; t < 4096; t += 320) {
        int bl = t >> 6, rem = t & 63;
        float v = x[(size_t)(b0 + bl) * (I_ * K_) + i0 * K_ + rem];
        sx[t] = pack2(v, v);
    }

    const int dq   = tid & 3;
    const int n    = (tid >> 2) % 10;
    const int iloc = tid / 40;

    // W regs: w2[k][p] = (W[d0+2p, k], W[d0+2p+1, k]), d0 = dq*4
    unsigned long long w2[8][2];
    {
        const float4* wp = (const float4*)(W +
            (((size_t)n * I_ + i0 + iloc) * D_ + dq * 4) * K_);
        float4 r0a = wp[0], r0b = wp[1];
        float4 r1a = wp[2], r1b = wp[3];
        float4 r2a = wp[4], r2b = wp[5];
        float4 r3a = wp[6], r3b = wp[7];
        w2[0][0] = pack2(r0a.x, r1a.x); w2[1][0] = pack2(r0a.y, r1a.y);
        w2[2][0] = pack2(r0a.z, r1a.z); w2[3][0] = pack2(r0a.w, r1a.w);
        w2[4][0] = pack2(r0b.x, r1b.x); w2[5][0] = pack2(r0b.y, r1b.y);
        w2[6][0] = pack2(r0b.z, r1b.z); w2[7][0] = pack2(r0b.w, r1b.w);
        w2[0][1] = pack2(r2a.x, r3a.x); w2[1][1] = pack2(r2a.y, r3a.y);
        w2[2][1] = pack2(r2a.z, r3a.z); w2[3][1] = pack2(r2a.w, r3a.w);
        w2[4][1] = pack2(r2b.x, r3b.x); w2[5][1] = pack2(r2b.y, r3b.y);
        w2[6][1] = pack2(r2b.z, r3b.z); w2[7][1] = pack2(r2b.w, r3b.w);
    }
    __syncthreads();

    __half* gout = g_uhat +
        (((size_t)b0 * N_ + n) * I_ + i0 + iloc) * D_ + dq * 4;
    const size_t bstride = (size_t)N_ * I_ * D_;

#pragma unroll 2
    for (int bl = 0; bl < 64; bl++) {
        const unsigned long long* xr = sx + bl * 64 + iloc * 8;
        unsigned long long a0 = 0ull, a1 = 0ull;
#pragma unroll
        for (int k = 0; k < 8; k++) {
            unsigned long long xx = xr[k];
            a0 = fma2(w2[k][0], xx, a0);
            a1 = fma2(w2[k][1], xx, a1);
        }
        uint2 r;
        r.x = cvt2h(a0);
        r.y = cvt2h(a1);
        *(uint2*)(gout + (size_t)bl * bstride) = r;
    }
}

// ---------------- kernel 2: fused routing, 4-CTA cluster per b ----------------
#define RT_THREADS 288
#define QI_ 288
#define NSTRIDE 2312                  // u32 words per n-block (288*8 + pad)
#define U_WORDS (N_ * NSTRIDE)        // 23120
#define CB_WORDS 2920                 // c[n][i] stride 292 (union: sPart 9*168)
#define SMEM_WORDS (U_WORDS + CB_WORDS + 2 * 160 + 160 + 160)
#define SMEM_BYTES (SMEM_WORDS * 4)   // 106,720 B -> 2 CTAs/SM

__global__ __launch_bounds__(RT_THREADS, 2) __cluster_dims__(4, 1, 1)
void k_route_all(float* __restrict__ out) {
    extern __shared__ unsigned int smem[];
    float* smf = (float*)smem;
    const int tid = threadIdx.x;
    const int b = blockIdx.x >> 2;
    unsigned int rank;
    asm("mov.u32 %0, %%cluster_ctarank;" : "=r"(rank));

    // load u slice [n][i_local][d], contiguous per n
    for (int t = tid; t < 5760; t += RT_THREADS) {
        int n   = t / 576;
        int rem = t - n * 576;
        const uint4* gp = (const uint4*)g_uhat +
            (((size_t)b * N_ + n) * I_ + rank * QI_) * 2 + rem;
        uint4 v = *gp;
        int il = rem >> 1, dh = rem & 1;
        *(uint4*)&smem[n * NSTRIDE + il * 8 + dh * 4] = v;
    }

    float* cbuf  = smf + U_WORDS;        // c[n][i], stride 292
    float* sPart = cbuf;                 // union (guarded by syncthreads)
    float* ssum  = smf + U_WORDS + CB_WORDS;  // [2][160]
    float* stot  = ssum + 320;
    float* ocum  = stot + 160;

    unsigned int ssum_sa = (unsigned int)__cvta_generic_to_shared(ssum);
    unsigned int peer[3];
#pragma unroll
    for (int p = 0; p < 3; p++)
        asm("mapa.shared::cluster.u32 %0, %1, %2;"
            : "=r"(peer[p]) : "r"(ssum_sa), "r"(rank ^ (unsigned)(p + 1)));

    const int w = tid >> 5, lane = tid & 31;
    const int il = lane >> 2, dq = lane & 3;

    __syncthreads();

#pragma unroll 1
    for (int r = 0; r < 3; r++) {
        // ---- sweep A: per-thread softmax coefficients (r >= 1) ----
        if (r > 0) {
            float lg[N_];
#pragma unroll
            for (int n = 0; n < N_; n++) {
                const unsigned int* up = &smem[n * NSTRIDE + tid * 8];
                uint4 v0 = *(const uint4*)up;
                uint4 v1 = *(const uint4*)(up + 4);
                const float4* op = (const float4*)&ocum[n * 16];
                float4 o0 = op[0], o1 = op[1], o2 = op[2], o3 = op[3];
                float2 a0 = __half22float2(*(const __half2*)&v0.x);
                float2 a1 = __half22float2(*(const __half2*)&v0.y);
                float2 a2 = __half22float2(*(const __half2*)&v0.z);
                float2 a3 = __half22float2(*(const __half2*)&v0.w);
                float2 a4 = __half22float2(*(const __half2*)&v1.x);
                float2 a5 = __half22float2(*(const __half2*)&v1.y);
                float2 a6 = __half22float2(*(const __half2*)&v1.z);
                float2 a7 = __half22float2(*(const __half2*)&v1.w);
                float p0 = a0.x * o0.x + a0.y * o0.y + a1.x * o0.z + a1.y * o0.w;
                float p1 = a2.x * o1.x + a2.y * o1.y + a3.x * o1.z + a3.y * o1.w;
                float p2 = a4.x * o2.x + a4.y * o2.y + a5.x * o2.z + a5.y * o2.w;
                float p3 = a6.x * o3.x + a6.y * o3.y + a7.x * o3.z + a7.y * o3.w;
                lg[n] = (p0 + p1) + (p2 + p3);
            }
            float m = lg[0];
#pragma unroll
            for (int n = 1; n < N_; n++) m = fmaxf(m, lg[n]);
            float sum = 0.0f;
#pragma unroll
            for (int n = 0; n < N_; n++) { lg[n] = __expf(lg[n] - m); sum += lg[n]; }
            float inv = __fdividef(1.0f, sum);
#pragma unroll
            for (int n = 0; n < N_; n++)
                cbuf[n * 292 + tid] = lg[n] * inv;
            __syncthreads();
        }

        // ---- sweep B: weighted accumulation ----
        float sp[N_][4];
#pragma unroll
        for (int n = 0; n < N_; n++)
#pragma unroll
            for (int q = 0; q < 4; q++) sp[n][q] = 0.0f;

#pragma unroll 1
        for (int round = 0; round < 4; round++) {
            const int iL = round * 72 + w * 8 + il;
            const int abase = iL * 8 + dq * 2;
#pragma unroll
            for (int n = 0; n < N_; n++) {
                uint2 v = *(const uint2*)&smem[n * NSTRIDE + abase];
                float2 f0 = __half22float2(*(const __half2*)&v.x);
                float2 f1 = __half22float2(*(const __half2*)&v.y);
                float cv = (r == 0) ? 0.1f : cbuf[n * 292 + iL];
                sp[n][0] += cv * f0.x;
                sp[n][1] += cv * f0.y;
                sp[n][2] += cv * f1.x;
                sp[n][3] += cv * f1.y;
            }
        }
        __syncthreads();   // all cbuf reads done before sPart overwrite (union)

        // reduce sp over il lanes
#pragma unroll
        for (int ofs = 4; ofs <= 16; ofs <<= 1)
#pragma unroll
            for (int n = 0; n < N_; n++)
#pragma unroll
                for (int q = 0; q < 4; q++)
                    sp[n][q] += __shfl_xor_sync(0xffffffffu, sp[n][q], ofs);

        if (il == 0) {
#pragma unroll
            for (int n = 0; n < N_; n++)
                *(float4*)&sPart[w * 168 + n * 16 + dq * 4] =
                    make_float4(sp[n][0], sp[n][1], sp[n][2], sp[n][3]);
        }
        __syncthreads();

        const int buf = r & 1;
        if (tid < 160) {
            float s = 0.0f;
#pragma unroll
            for (int ww = 0; ww < 9; ww++) s += sPart[ww * 168 + tid];
            ssum[buf * 160 + tid] = s;
        }
        asm volatile("barrier.cluster.arrive.aligned;" ::: "memory");
        asm volatile("barrier.cluster.wait.aligned;" ::: "memory");

        if (tid < 160) {
            float tot = ssum[buf * 160 + tid];
#pragma unroll
            for (int p = 0; p < 3; p++) {
                float pv;
                unsigned int pa = peer[p] + (unsigned int)(buf * 160 + tid) * 4u;
                asm volatile("ld.shared::cluster.f32 %0, [%1];" : "=f"(pv) : "r"(pa));
                tot += pv;
            }
            stot[tid] = tot;
        }
        __syncthreads();

        if (tid < 160) {
            const int n = tid >> 4;
            float ns = 0.0f;
#pragma unroll
            for (int j = 0; j < 16; j++) {
                float t = stot[n * 16 + j];
                ns += t * t;
            }
            float f = sqrtf(ns) / (1.0f + ns);
            float val = stot[tid] * f;
            if (r < 2) ocum[tid] = (r == 0) ? val : ocum[tid] + val;
            else if (rank == 0) out[b * 160 + tid] = val;
        }
        __syncthreads();
    }
    asm volatile("barrier.cluster.arrive.aligned;" ::: "memory");
    asm volatile("barrier.cluster.wait.aligned;" ::: "memory");
}

// ---------------- launch ----------------
extern "C" void kernel_launch(void* const* d_in, const int* in_sizes, int n_in,
                              void* d_out, int out_size) {
    const float* x = (const float*)d_in[0];   // inputs [B, I, Din]
    const float* W = (const float*)d_in[1];   // W      [N, I, D, Din]
    if (n_in >= 2 && in_sizes[0] == N_ * I_ * D_ * K_) {
        const float* t = x; x = W; W = t;
    }
    float* out = (float*)d_out;

    cudaFuncSetAttribute(k_route_all,
                         cudaFuncAttributeMaxDynamicSharedMemorySize, SMEM_BYTES);

    k_uhat<<<576, 320>>>(x, W);
    k_route_all<<<4 * B_, RT_THREADS, SMEM_BYTES>>>(out);
}

// round 8
// speedup vs baseline: 1.0151x; 1.0151x over previous
#include <cuda_runtime.h>
#include <cuda_fp16.h>
#include <cstdint>

#define B_ 256
#define I_ 1152
#define N_ 10
#define D_ 16
#define K_ 8

// u_hat scratch, layout [b][n][i][d], fp16 = 94 MB
__device__ __half g_uhat[(size_t)B_ * N_ * I_ * D_];

// ---------------- helpers ----------------
__device__ __forceinline__ unsigned long long pack2(float a, float b) {
    unsigned long long r;
    asm("mov.b64 %0, {%1, %2};" : "=l"(r) : "f"(a), "f"(b));
    return r;
}
__device__ __forceinline__ unsigned long long fma2(unsigned long long a,
                                                   unsigned long long b,
                                                   unsigned long long c) {
    unsigned long long r;
    asm("fma.rn.f32x2 %0, %1, %2, %3;" : "=l"(r) : "l"(a), "l"(b), "l"(c));
    return r;
}
__device__ __forceinline__ unsigned int cvt2h(unsigned long long v) {
    float lo, hi;
    asm("mov.b64 {%0, %1}, %2;" : "=f"(lo), "=f"(hi) : "l"(v));
    __half2 h = __floats2half2_rn(lo, hi);
    return *reinterpret_cast<unsigned int*>(&h);
}

// ---------------- kernel 1: u_hat = einsum('nidk,bik->bnid') fp16 -------------
// Grid 576 = 144 i-groups x 4 b-quarters. 320 threads = (iloc 8) x (n 10) x (dq 4).
// x staged in smem duplicated as (x,x) u64 -> hot-loop LDS.64 is warp-broadcast.
// W held in registers (16 u64 of d-paired values).
__global__ __launch_bounds__(320, 2) void k_uhat(const float* __restrict__ x,
                                                 const float* __restrict__ W) {
    __shared__ unsigned long long sx[64 * 64];  // [bl][il*8+k], 32 KB
    const int tid = threadIdx.x;
    const int ig = blockIdx.x >> 2;
    const int bq = blockIdx.x & 3;
    const int i0 = ig * 8;
    const int b0 = bq * 64;

    // stage x (fully coalesced reads), duplicate each float into u64 lanes
    for (int t = tid; t < 4096; t += 320) {
        int bl = t >> 6, rem = t & 63;
        float v = x[(size_t)(b0 + bl) * (I_ * K_) + i0 * K_ + rem];
        sx[t] = pack2(v, v);
    }

    const int dq   = tid & 3;
    const int n    = (tid >> 2) % 10;
    const int iloc = tid / 40;

    // W regs: w2[k][p] = (W[d0+2p, k], W[d0+2p+1, k]), d0 = dq*4
    unsigned long long w2[8][2];
    {
        const float4* wp = (const float4*)(W +
            (((size_t)n * I_ + i0 + iloc) * D_ + dq * 4) * K_);
        float4 r0a = wp[0], r0b = wp[1];
        float4 r1a = wp[2], r1b = wp[3];
        float4 r2a = wp[4], r2b = wp[5];
        float4 r3a = wp[6], r3b = wp[7];
        w2[0][0] = pack2(r0a.x, r1a.x); w2[1][0] = pack2(r0a.y, r1a.y);
        w2[2][0] = pack2(r0a.z, r1a.z); w2[3][0] = pack2(r0a.w, r1a.w);
        w2[4][0] = pack2(r0b.x, r1b.x); w2[5][0] = pack2(r0b.y, r1b.y);
        w2[6][0] = pack2(r0b.z, r1b.z); w2[7][0] = pack2(r0b.w, r1b.w);
        w2[0][1] = pack2(r2a.x, r3a.x); w2[1][1] = pack2(r2a.y, r3a.y);
        w2[2][1] = pack2(r2a.z, r3a.z); w2[3][1] = pack2(r2a.w, r3a.w);
        w2[4][1] = pack2(r2b.x, r3b.x); w2[5][1] = pack2(r2b.y, r3b.y);
        w2[6][1] = pack2(r2b.z, r3b.z); w2[7][1] = pack2(r2b.w, r3b.w);
    }
    __syncthreads();

    __half* gout = g_uhat +
        (((size_t)b0 * N_ + n) * I_ + i0 + iloc) * D_ + dq * 4;
    const size_t bstride = (size_t)N_ * I_ * D_;

#pragma unroll 2
    for (int bl = 0; bl < 64; bl++) {
        const unsigned long long* xr = sx + bl * 64 + iloc * 8;
        unsigned long long a0 = 0ull, a1 = 0ull;
#pragma unroll
        for (int k = 0; k < 8; k++) {
            unsigned long long xx = xr[k];
            a0 = fma2(w2[k][0], xx, a0);
            a1 = fma2(w2[k][1], xx, a1);
        }
        uint2 r;
        r.x = cvt2h(a0);
        r.y = cvt2h(a1);
        *(uint2*)(gout + (size_t)bl * bstride) = r;
    }
}

// ---------------- kernel 2: fused routing, 4-CTA cluster per b ----------------
#define RT_THREADS 288
#define QI_ 288
#define NSTRIDE 2312                  // u32 words per n-block (288*8 + pad)
#define U_WORDS (N_ * NSTRIDE)        // 23120
#define CB_WORDS 2920                 // c[n][i] stride 292 (union: sPart 9*168)
#define SMEM_WORDS (U_WORDS + CB_WORDS + 2 * 160 + 160 + 160)
#define SMEM_BYTES (SMEM_WORDS * 4)   // 106,720 B -> 2 CTAs/SM

__global__ __launch_bounds__(RT_THREADS, 2) __cluster_dims__(4, 1, 1)
void k_route_all(float* __restrict__ out) {
    extern __shared__ unsigned int smem[];
    float* smf = (float*)smem;
    const int tid = threadIdx.x;
    const int b = blockIdx.x >> 2;
    unsigned int rank;
    asm("mov.u32 %0, %%cluster_ctarank;" : "=r"(rank));

    // load u slice [n][i_local][d], contiguous per n
    for (int t = tid; t < 5760; t += RT_THREADS) {
        int n   = t / 576;
        int rem = t - n * 576;
        const uint4* gp = (const uint4*)g_uhat +
            (((size_t)b * N_ + n) * I_ + rank * QI_) * 2 + rem;
        uint4 v = *gp;
        int il = rem >> 1, dh = rem & 1;
        *(uint4*)&smem[n * NSTRIDE + il * 8 + dh * 4] = v;
    }

    float* cbuf  = smf + U_WORDS;        // c[n][i], stride 292
    float* sPart = cbuf;                 // union (guarded by syncthreads)
    float* ssum  = smf + U_WORDS + CB_WORDS;  // [2][160]
    float* stot  = ssum + 320;
    float* ocum  = stot + 160;

    unsigned int ssum_sa = (unsigned int)__cvta_generic_to_shared(ssum);
    unsigned int peer[3];
#pragma unroll
    for (int p = 0; p < 3; p++)
        asm("mapa.shared::cluster.u32 %0, %1, %2;"
            : "=r"(peer[p]) : "r"(ssum_sa), "r"(rank ^ (unsigned)(p + 1)));

    const int w = tid >> 5, lane = tid & 31;
    const int il = lane >> 2, dq = lane & 3;

    __syncthreads();

#pragma unroll 1
    for (int r = 0; r < 3; r++) {
        // ---- sweep A: per-thread softmax coefficients (r >= 1) ----
        if (r > 0) {
            float lg[N_];
#pragma unroll
            for (int n = 0; n < N_; n++) {
                const unsigned int* up = &smem[n * NSTRIDE + tid * 8];
                uint4 v0 = *(const uint4*)up;
                uint4 v1 = *(const uint4*)(up + 4);
                const float4* op = (const float4*)&ocum[n * 16];
                float4 o0 = op[0], o1 = op[1], o2 = op[2], o3 = op[3];
                float2 a0 = __half22float2(*(const __half2*)&v0.x);
                float2 a1 = __half22float2(*(const __half2*)&v0.y);
                float2 a2 = __half22float2(*(const __half2*)&v0.z);
                float2 a3 = __half22float2(*(const __half2*)&v0.w);
                float2 a4 = __half22float2(*(const __half2*)&v1.x);
                float2 a5 = __half22float2(*(const __half2*)&v1.y);
                float2 a6 = __half22float2(*(const __half2*)&v1.z);
                float2 a7 = __half22float2(*(const __half2*)&v1.w);
                float p0 = a0.x * o0.x + a0.y * o0.y + a1.x * o0.z + a1.y * o0.w;
                float p1 = a2.x * o1.x + a2.y * o1.y + a3.x * o1.z + a3.y * o1.w;
                float p2 = a4.x * o2.x + a4.y * o2.y + a5.x * o2.z + a5.y * o2.w;
                float p3 = a6.x * o3.x + a6.y * o3.y + a7.x * o3.z + a7.y * o3.w;
                lg[n] = (p0 + p1) + (p2 + p3);
            }
            float m = lg[0];
#pragma unroll
            for (int n = 1; n < N_; n++) m = fmaxf(m, lg[n]);
            float sum = 0.0f;
#pragma unroll
            for (int n = 0; n < N_; n++) { lg[n] = __expf(lg[n] - m); sum += lg[n]; }
            float inv = __fdividef(1.0f, sum);
#pragma unroll
            for (int n = 0; n < N_; n++)
                cbuf[n * 292 + tid] = lg[n] * inv;
            __syncthreads();
        }

        // ---- sweep B: weighted accumulation ----
        float sp[N_][4];
#pragma unroll
        for (int n = 0; n < N_; n++)
#pragma unroll
            for (int q = 0; q < 4; q++) sp[n][q] = 0.0f;

#pragma unroll 1
        for (int round = 0; round < 4; round++) {
            const int iL = round * 72 + w * 8 + il;
            const int abase = iL * 8 + dq * 2;
#pragma unroll
            for (int n = 0; n < N_; n++) {
                uint2 v = *(const uint2*)&smem[n * NSTRIDE + abase];
                float2 f0 = __half22float2(*(const __half2*)&v.x);
                float2 f1 = __half22float2(*(const __half2*)&v.y);
                float cv = (r == 0) ? 0.1f : cbuf[n * 292 + iL];
                sp[n][0] += cv * f0.x;
                sp[n][1] += cv * f0.y;
                sp[n][2] += cv * f1.x;
                sp[n][3] += cv * f1.y;
            }
        }
        __syncthreads();   // all cbuf reads done before sPart overwrite (union)

        // reduce sp over il lanes
#pragma unroll
        for (int ofs = 4; ofs <= 16; ofs <<= 1)
#pragma unroll
            for (int n = 0; n < N_; n++)
#pragma unroll
                for (int q = 0; q < 4; q++)
                    sp[n][q] += __shfl_xor_sync(0xffffffffu, sp[n][q], ofs);

        if (il == 0) {
#pragma unroll
            for (int n = 0; n < N_; n++)
                *(float4*)&sPart[w * 168 + n * 16 + dq * 4] =
                    make_float4(sp[n][0], sp[n][1], sp[n][2], sp[n][3]);
        }
        __syncthreads();

        const int buf = r & 1;
        if (tid < 160) {
            float s = 0.0f;
#pragma unroll
            for (int ww = 0; ww < 9; ww++) s += sPart[ww * 168 + tid];
            ssum[buf * 160 + tid] = s;
        }
        asm volatile("barrier.cluster.arrive.aligned;" ::: "memory");
        asm volatile("barrier.cluster.wait.aligned;" ::: "memory");

        if (tid < 160) {
            float tot = ssum[buf * 160 + tid];
#pragma unroll
            for (int p = 0; p < 3; p++) {
                float pv;
                unsigned int pa = peer[p] + (unsigned int)(buf * 160 + tid) * 4u;
                asm volatile("ld.shared::cluster.f32 %0, [%1];" : "=f"(pv) : "r"(pa));
                tot += pv;
            }
            stot[tid] = tot;
        }
        __syncthreads();

        if (tid < 160) {
            const int n = tid >> 4;
            float ns = 0.0f;
#pragma unroll
            for (int j = 0; j < 16; j++) {
                float t = stot[n * 16 + j];
                ns += t * t;
            }
            float f = sqrtf(ns) / (1.0f + ns);
            float val = stot[tid] * f;
            if (r < 2) ocum[tid] = (r == 0) ? val : ocum[tid] + val;
            else if (rank == 0) out[b * 160 + tid] = val;
        }
        __syncthreads();
    }
    asm volatile("barrier.cluster.arrive.aligned;" ::: "memory");
    asm volatile("barrier.cluster.wait.aligned;" ::: "memory");
}

// ---------------- launch ----------------
extern "C" void kernel_launch(void* const* d_in, const int* in_sizes, int n_in,
                              void* d_out, int out_size) {
    const float* x = (const float*)d_in[0];   // inputs [B, I, Din]
    const float* W = (const float*)d_in[1];   // W      [N, I, D, Din]
    if (n_in >= 2 && in_sizes[0] == N_ * I_ * D_ * K_) {
        const float* t = x; x = W; W = t;
    }
    float* out = (float*)d_out;

    cudaFuncSetAttribute(k_route_all,
                         cudaFuncAttributeMaxDynamicSharedMemorySize, SMEM_BYTES);

    k_uhat<<<576, 320>>>(x, W);
    k_route_all<<<4 * B_, RT_THREADS, SMEM_BYTES>>>(out);
}

// round 9
// speedup vs baseline: 1.3656x; 1.3453x over previous
#include <cuda_runtime.h>
#include <cuda_fp16.h>
#include <cstdint>

#define B_ 256
#define I_ 1152
#define N_ 10
#define D_ 16
#define K_ 8

// u_hat scratch, layout [b][n][i][d], fp16 = 94 MB (L2-resident)
__device__ __half g_uhat[(size_t)B_ * N_ * I_ * D_];

// ---------------- helpers ----------------
__device__ __forceinline__ unsigned long long pack2(float a, float b) {
    unsigned long long r;
    asm("mov.b64 %0, {%1, %2};" : "=l"(r) : "f"(a), "f"(b));
    return r;
}
__device__ __forceinline__ unsigned long long fma2(unsigned long long a,
                                                   unsigned long long b,
                                                   unsigned long long c) {
    unsigned long long r;
    asm("fma.rn.f32x2 %0, %1, %2, %3;" : "=l"(r) : "l"(a), "l"(b), "l"(c));
    return r;
}
__device__ __forceinline__ unsigned int cvt2h(unsigned long long v) {
    float lo, hi;
    asm("mov.b64 {%0, %1}, %2;" : "=f"(lo), "=f"(hi) : "l"(v));
    __half2 h = __floats2half2_rn(lo, hi);
    return *reinterpret_cast<unsigned int*>(&h);
}

// ---------------- kernel 1: u_hat = einsum('nidk,bik->bnid') fp16 -------------
// Grid 144 (one CTA per 8-i group, ALL 256 b) -> W read exactly once.
// 640 threads: bh = tid/320 (b-half of chunk), t = tid%320 = (iloc 8, n 10, dq 4).
// x staged per 64-b chunk as (x,x)-duplicated u64 -> hot LDS.64 is broadcast.
__global__ __launch_bounds__(640, 1) void k_uhat(const float* __restrict__ x,
                                                 const float* __restrict__ W) {
    __shared__ unsigned long long sx[64 * 64];  // 32 KB: [bl][iloc*8+k]
    const int tid = threadIdx.x;
    const int i0 = blockIdx.x * 8;

    const int bh   = tid >= 320;
    const int t    = tid - bh * 320;
    const int dq   = t & 3;
    const int n    = (t >> 2) % 10;
    const int iloc = t / 40;

    // W regs: w2[k][p] = (W[d0+2p? ...], packed d-pairs), d0 = dq*4
    unsigned long long w2[8][2];
    {
        const float4* wp = (const float4*)(W +
            (((size_t)n * I_ + i0 + iloc) * D_ + dq * 4) * K_);
        float4 r0a = wp[0], r0b = wp[1];
        float4 r1a = wp[2], r1b = wp[3];
        float4 r2a = wp[4], r2b = wp[5];
        float4 r3a = wp[6], r3b = wp[7];
        w2[0][0] = pack2(r0a.x, r1a.x); w2[1][0] = pack2(r0a.y, r1a.y);
        w2[2][0] = pack2(r0a.z, r1a.z); w2[3][0] = pack2(r0a.w, r1a.w);
        w2[4][0] = pack2(r0b.x, r1b.x); w2[5][0] = pack2(r0b.y, r1b.y);
        w2[6][0] = pack2(r0b.z, r1b.z); w2[7][0] = pack2(r0b.w, r1b.w);
        w2[0][1] = pack2(r2a.x, r3a.x); w2[1][1] = pack2(r2a.y, r3a.y);
        w2[2][1] = pack2(r2a.z, r3a.z); w2[3][1] = pack2(r2a.w, r3a.w);
        w2[4][1] = pack2(r2b.x, r3b.x); w2[5][1] = pack2(r2b.y, r3b.y);
        w2[6][1] = pack2(r2b.z, r3b.z); w2[7][1] = pack2(r2b.w, r3b.w);
    }

    const size_t bstride = (size_t)N_ * I_ * D_;

#pragma unroll 1
    for (int c = 0; c < 4; c++) {
        __syncthreads();
        // stage x chunk: b in [c*64, c*64+64), 64 floats per b (8 i x 8 k)
        for (int idx = tid; idx < 4096; idx += 640) {
            int bl = idx >> 6, rem = idx & 63;
            float v = x[(size_t)(c * 64 + bl) * (I_ * K_) + i0 * K_ + rem];
            sx[idx] = pack2(v, v);
        }
        __syncthreads();

        const int blo = bh * 32;
#pragma unroll 2
        for (int j = 0; j < 32; j++) {
            const int bl = blo + j;
            const unsigned long long* xr = sx + bl * 64 + iloc * 8;
            unsigned long long a0 = 0ull, a1 = 0ull;
#pragma unroll
            for (int k = 0; k < 8; k++) {
                unsigned long long xx = xr[k];
                a0 = fma2(w2[k][0], xx, a0);
                a1 = fma2(w2[k][1], xx, a1);
            }
            uint2 r;
            r.x = cvt2h(a0);
            r.y = cvt2h(a1);
            const int b = c * 64 + bl;
            *(uint2*)(g_uhat + ((size_t)b * bstride) +
                      ((size_t)n * I_ + i0 + iloc) * D_ + dq * 4) = r;
        }
    }
}

// ---------------- kernel 2: routing, one CTA per b, u streamed from L2 --------
#define RTH 384
#define CHUNK_I 288

__global__ __launch_bounds__(RTH, 2) void k_route(float* __restrict__ out) {
    __shared__ __align__(16) float cbuf[10 * 296];   // c[n][i-in-chunk]
    __shared__ __align__(16) float sPart[12 * 168];
    __shared__ __align__(16) float stot[160];
    __shared__ __align__(16) float ocum[160];

    const int tid = threadIdx.x;
    const int b = blockIdx.x;
    const __half* ub = g_uhat + (size_t)b * N_ * I_ * D_;

    const int w = tid >> 5, lane = tid & 31;
    const int il = lane >> 2, dq = lane & 3;

#pragma unroll 1
    for (int r = 0; r < 3; r++) {
        float sp[N_][4];
#pragma unroll
        for (int n = 0; n < N_; n++)
#pragma unroll
            for (int q = 0; q < 4; q++) sp[n][q] = 0.0f;

#pragma unroll 1
        for (int chunk = 0; chunk < 4; chunk++) {
            // ---- sweep A: softmax coefficients for this chunk (r >= 1) ----
            if (r > 0) {
                if (tid < CHUNK_I) {
                    const int i = chunk * CHUNK_I + tid;
                    float lg[N_];
#pragma unroll
                    for (int n = 0; n < N_; n++) {
                        const uint4* p = (const uint4*)(ub + ((size_t)n * I_ + i) * D_);
                        uint4 v0 = p[0], v1 = p[1];
                        const float4* op = (const float4*)&ocum[n * 16];
                        float4 o0 = op[0], o1 = op[1], o2 = op[2], o3 = op[3];
                        float2 a0 = __half22float2(*(const __half2*)&v0.x);
                        float2 a1 = __half22float2(*(const __half2*)&v0.y);
                        float2 a2 = __half22float2(*(const __half2*)&v0.z);
                        float2 a3 = __half22float2(*(const __half2*)&v0.w);
                        float2 a4 = __half22float2(*(const __half2*)&v1.x);
                        float2 a5 = __half22float2(*(const __half2*)&v1.y);
                        float2 a6 = __half22float2(*(const __half2*)&v1.z);
                        float2 a7 = __half22float2(*(const __half2*)&v1.w);
                        float p0 = a0.x * o0.x + a0.y * o0.y + a1.x * o0.z + a1.y * o0.w;
                        float p1 = a2.x * o1.x + a2.y * o1.y + a3.x * o1.z + a3.y * o1.w;
                        float p2 = a4.x * o2.x + a4.y * o2.y + a5.x * o2.z + a5.y * o2.w;
                        float p3 = a6.x * o3.x + a6.y * o3.y + a7.x * o3.z + a7.y * o3.w;
                        lg[n] = (p0 + p1) + (p2 + p3);
                    }
                    float m = lg[0];
#pragma unroll
                    for (int n = 1; n < N_; n++) m = fmaxf(m, lg[n]);
                    float sum = 0.0f;
#pragma unroll
                    for (int n = 0; n < N_; n++) { lg[n] = __expf(lg[n] - m); sum += lg[n]; }
                    float inv = __fdividef(1.0f, sum);
#pragma unroll
                    for (int n = 0; n < N_; n++) cbuf[n * 296 + tid] = lg[n] * inv;
                }
                __syncthreads();
            }

            // ---- sweep B: weighted accumulation (u re-read hits L1) ----
#pragma unroll 1
            for (int round = 0; round < 3; round++) {
                const int ic = round * 96 + w * 8 + il;        // i in chunk
                const int iL = chunk * CHUNK_I + ic;
                const __half* ubase = ub + (size_t)iL * D_ + dq * 4;
#pragma unroll
                for (int n = 0; n < N_; n++) {
                    uint2 v = *(const uint2*)(ubase + (size_t)n * (I_ * D_));
                    float2 f0 = __half22float2(*(const __half2*)&v.x);
                    float2 f1 = __half22float2(*(const __half2*)&v.y);
                    float cv = (r == 0) ? 0.1f : cbuf[n * 296 + ic];
                    sp[n][0] += cv * f0.x;
                    sp[n][1] += cv * f0.y;
                    sp[n][2] += cv * f1.x;
                    sp[n][3] += cv * f1.y;
                }
            }
            __syncthreads();   // cbuf consumed before next chunk overwrites
        }

        // ---- CTA reduction: sp over il lanes, then over 12 warps ----
#pragma unroll
        for (int ofs = 4; ofs <= 16; ofs <<= 1)
#pragma unroll
            for (int n = 0; n < N_; n++)
#pragma unroll
                for (int q = 0; q < 4; q++)
                    sp[n][q] += __shfl_xor_sync(0xffffffffu, sp[n][q], ofs);

        if (il == 0) {
#pragma unroll
            for (int n = 0; n < N_; n++)
                *(float4*)&sPart[w * 168 + n * 16 + dq * 4] =
                    make_float4(sp[n][0], sp[n][1], sp[n][2], sp[n][3]);
        }
        __syncthreads();

        if (tid < 160) {
            float s = 0.0f;
#pragma unroll
            for (int ww = 0; ww < 12; ww++) s += sPart[ww * 168 + tid];
            stot[tid] = s;
        }
        __syncthreads();

        if (tid < 160) {
            const int n = tid >> 4;
            float ns = 0.0f;
#pragma unroll
            for (int j = 0; j < 16; j++) {
                float tv = stot[n * 16 + j];
                ns += tv * tv;
            }
            float f = sqrtf(ns) / (1.0f + ns);
            float val = stot[tid] * f;
            if (r < 2) ocum[tid] = (r == 0) ? val : ocum[tid] + val;
            else       out[b * 160 + tid] = val;
        }
        __syncthreads();
    }
}

// ---------------- launch ----------------
extern "C" void kernel_launch(void* const* d_in, const int* in_sizes, int n_in,
                              void* d_out, int out_size) {
    const float* x = (const float*)d_in[0];   // inputs [B, I, Din]
    const float* W = (const float*)d_in[1];   // W      [N, I, D, Din]
    if (n_in >= 2 && in_sizes[0] == N_ * I_ * D_ * K_) {
        const float* t = x; x = W; W = t;
    }
    float* out = (float*)d_out;

    k_uhat<<<144, 640>>>(x, W);
    k_route<<<B_, RTH>>>(out);
}

// round 10
// speedup vs baseline: 1.5194x; 1.1126x over previous
#include <cuda_runtime.h>
#include <cuda_fp16.h>
#include <cstdint>

#define B_ 256
#define I_ 1152
#define N_ 10
#define D_ 16
#define K_ 8

// u_hat scratch, layout [b][n][i][d], fp16 = 94 MB (L2-resident)
__device__ __half g_uhat[(size_t)B_ * N_ * I_ * D_];

// ---------------- helpers ----------------
__device__ __forceinline__ unsigned long long pack2(float a, float b) {
    unsigned long long r;
    asm("mov.b64 %0, {%1, %2};" : "=l"(r) : "f"(a), "f"(b));
    return r;
}
__device__ __forceinline__ unsigned long long fma2(unsigned long long a,
                                                   unsigned long long b,
                                                   unsigned long long c) {
    unsigned long long r;
    asm("fma.rn.f32x2 %0, %1, %2, %3;" : "=l"(r) : "l"(a), "l"(b), "l"(c));
    return r;
}
__device__ __forceinline__ unsigned int cvt2h(unsigned long long v) {
    float lo, hi;
    asm("mov.b64 {%0, %1}, %2;" : "=f"(lo), "=f"(hi) : "l"(v));
    __half2 h = __floats2half2_rn(lo, hi);
    return *reinterpret_cast<unsigned int*>(&h);
}

// ---------------- kernel 1: u_hat = einsum('nidk,bik->bnid') fp16 -------------
// Grid 288 (one CTA per 4-i group, ALL 256 b) -> W read exactly once.
// 320 threads: bh = tid/160, t = tid%160 = (iloc 4, n 10, dq 4).
__global__ __launch_bounds__(320, 2) void k_uhat(const float* __restrict__ x,
                                                 const float* __restrict__ W) {
    __shared__ unsigned long long sx[64 * 32];  // 16 KB: [bl][iloc*8+k]
    const int tid = threadIdx.x;
    const int i0 = blockIdx.x * 4;

    const int bh   = tid >= 160;
    const int t    = tid - bh * 160;
    const int dq   = t & 3;
    const int n    = (t >> 2) % 10;
    const int iloc = t / 40;                     // 0..3

    unsigned long long w2[8][2];
    {
        const float4* wp = (const float4*)(W +
            (((size_t)n * I_ + i0 + iloc) * D_ + dq * 4) * K_);
        float4 r0a = wp[0], r0b = wp[1];
        float4 r1a = wp[2], r1b = wp[3];
        float4 r2a = wp[4], r2b = wp[5];
        float4 r3a = wp[6], r3b = wp[7];
        w2[0][0] = pack2(r0a.x, r1a.x); w2[1][0] = pack2(r0a.y, r1a.y);
        w2[2][0] = pack2(r0a.z, r1a.z); w2[3][0] = pack2(r0a.w, r1a.w);
        w2[4][0] = pack2(r0b.x, r1b.x); w2[5][0] = pack2(r0b.y, r1b.y);
        w2[6][0] = pack2(r0b.z, r1b.z); w2[7][0] = pack2(r0b.w, r1b.w);
        w2[0][1] = pack2(r2a.x, r3a.x); w2[1][1] = pack2(r2a.y, r3a.y);
        w2[2][1] = pack2(r2a.z, r3a.z); w2[3][1] = pack2(r2a.w, r3a.w);
        w2[4][1] = pack2(r2b.x, r3b.x); w2[5][1] = pack2(r2b.y, r3b.y);
        w2[6][1] = pack2(r2b.z, r3b.z); w2[7][1] = pack2(r2b.w, r3b.w);
    }

    const size_t bstride = (size_t)N_ * I_ * D_;

#pragma unroll 1
    for (int c = 0; c < 4; c++) {
        __syncthreads();
        // stage x chunk: b in [c*64, c*64+64), 32 floats per b (4 i x 8 k)
        for (int idx = tid; idx < 2048; idx += 320) {
            int bl = idx >> 5, rem = idx & 31;
            float v = x[(size_t)(c * 64 + bl) * (I_ * K_) + i0 * K_ + rem];
            sx[idx] = pack2(v, v);
        }
        __syncthreads();

        const int blo = bh * 32;
#pragma unroll 2
        for (int j = 0; j < 32; j++) {
            const int bl = blo + j;
            const unsigned long long* xr = sx + bl * 32 + iloc * 8;
            unsigned long long a0 = 0ull, a1 = 0ull;
#pragma unroll
            for (int k = 0; k < 8; k++) {
                unsigned long long xx = xr[k];
                a0 = fma2(w2[k][0], xx, a0);
                a1 = fma2(w2[k][1], xx, a1);
            }
            uint2 r;
            r.x = cvt2h(a0);
            r.y = cvt2h(a1);
            const int b = c * 64 + bl;
            *(uint2*)(g_uhat + ((size_t)b * bstride) +
                      ((size_t)n * I_ + i0 + iloc) * D_ + dq * 4) = r;
        }
    }
}

// ---------------- kernel 2: routing, one 512-thread CTA per b -----------------
#define RTH 512
#define CHUNK_I 384

__global__ __launch_bounds__(RTH, 2) void k_route(float* __restrict__ out) {
    __shared__ __align__(16) float cbuf[10 * 388];     // c[n][i-in-chunk]
    __shared__ __align__(16) float sPart[16 * 80];
    __shared__ __align__(16) float stot[160];
    __shared__ __align__(16) float ocum[160];
    __shared__ __align__(16) unsigned int ocum_h[80];  // ocum as half2[d-pairs]

    const int tid = threadIdx.x;
    const int b = blockIdx.x;
    const __half* ub = g_uhat + (size_t)b * N_ * I_ * D_;

    const int w = tid >> 5, lane = tid & 31;
    const int il = lane >> 2, dq = lane & 3;
    const int nh = w & 1, wg = w >> 1;      // n-half, warp-group
    const int nbase = nh * 5;

#pragma unroll 1
    for (int r = 0; r < 3; r++) {
        float sp[5][4];
#pragma unroll
        for (int n = 0; n < 5; n++)
#pragma unroll
            for (int q = 0; q < 4; q++) sp[n][q] = 0.0f;

#pragma unroll 1
        for (int chunk = 0; chunk < 3; chunk++) {
            // ---- sweep A: softmax coefficients, fp16 dots (r >= 1) ----
            if (r > 0) {
                if (tid < CHUNK_I) {
                    const int i = chunk * CHUNK_I + tid;
                    float lg[10];
#pragma unroll 2
                    for (int n = 0; n < 10; n++) {
                        const uint4* p = (const uint4*)(ub + ((size_t)n * I_ + i) * D_);
                        uint4 v0 = p[0], v1 = p[1];
                        uint4 o0 = ((const uint4*)ocum_h)[n * 2];
                        uint4 o1 = ((const uint4*)ocum_h)[n * 2 + 1];
                        __half2 acc = __float2half2_rn(0.0f);
                        acc = __hfma2(*(const __half2*)&v0.x, *(const __half2*)&o0.x, acc);
                        acc = __hfma2(*(const __half2*)&v0.y, *(const __half2*)&o0.y, acc);
                        acc = __hfma2(*(const __half2*)&v0.z, *(const __half2*)&o0.z, acc);
                        acc = __hfma2(*(const __half2*)&v0.w, *(const __half2*)&o0.w, acc);
                        acc = __hfma2(*(const __half2*)&v1.x, *(const __half2*)&o1.x, acc);
                        acc = __hfma2(*(const __half2*)&v1.y, *(const __half2*)&o1.y, acc);
                        acc = __hfma2(*(const __half2*)&v1.z, *(const __half2*)&o1.z, acc);
                        acc = __hfma2(*(const __half2*)&v1.w, *(const __half2*)&o1.w, acc);
                        float2 fa = __half22float2(acc);
                        lg[n] = fa.x + fa.y;
                    }
                    float m = lg[0];
#pragma unroll
                    for (int n = 1; n < 10; n++) m = fmaxf(m, lg[n]);
                    float sum = 0.0f;
#pragma unroll
                    for (int n = 0; n < 10; n++) { lg[n] = __expf(lg[n] - m); sum += lg[n]; }
                    float inv = __fdividef(1.0f, sum);
#pragma unroll
                    for (int n = 0; n < 10; n++) cbuf[n * 388 + tid] = lg[n] * inv;
                }
                __syncthreads();
            }

            // ---- sweep B: weighted accumulation, 5 n per warp ----
#pragma unroll 2
            for (int round = 0; round < 6; round++) {
                const int ic = round * 64 + wg * 8 + il;      // i within chunk
                const __half* ubase = ub +
                    ((size_t)nbase * I_ + chunk * CHUNK_I + ic) * D_ + dq * 4;
#pragma unroll
                for (int n = 0; n < 5; n++) {
                    uint2 v = *(const uint2*)(ubase + (size_t)n * (I_ * D_));
                    float2 f0 = __half22float2(*(const __half2*)&v.x);
                    float2 f1 = __half22float2(*(const __half2*)&v.y);
                    float cv = (r == 0) ? 0.1f : cbuf[(nbase + n) * 388 + ic];
                    sp[n][0] += cv * f0.x;
                    sp[n][1] += cv * f0.y;
                    sp[n][2] += cv * f1.x;
                    sp[n][3] += cv * f1.y;
                }
            }
            if (r > 0) __syncthreads();   // cbuf consumed before next chunk
        }

        // ---- reduce sp over il lanes within warp ----
#pragma unroll
        for (int ofs = 4; ofs <= 16; ofs <<= 1)
#pragma unroll
            for (int n = 0; n < 5; n++)
#pragma unroll
                for (int q = 0; q < 4; q++)
                    sp[n][q] += __shfl_xor_sync(0xffffffffu, sp[n][q], ofs);

        if (il == 0) {
#pragma unroll
            for (int n = 0; n < 5; n++)
                *(float4*)&sPart[w * 80 + n * 16 + dq * 4] =
                    make_float4(sp[n][0], sp[n][1], sp[n][2], sp[n][3]);
        }
        __syncthreads();

        if (tid < 160) {
            const int n = tid >> 4;
            const int nh2 = (n >= 5);
            const int col = (n - nh2 * 5) * 16 + (tid & 15);
            float s = 0.0f;
#pragma unroll
            for (int j = 0; j < 8; j++) s += sPart[(j * 2 + nh2) * 80 + col];
            stot[tid] = s;
        }
        __syncthreads();

        if (tid < 160) {
            const int n = tid >> 4;
            float ns = 0.0f;
#pragma unroll
            for (int j = 0; j < 16; j++) {
                float tv = stot[n * 16 + j];
                ns += tv * tv;
            }
            float f = sqrtf(ns) / (1.0f + ns);
            float val = stot[tid] * f;
            if (r < 2) ocum[tid] = (r == 0) ? val : ocum[tid] + val;
            else       out[b * 160 + tid] = val;
        }
        __syncthreads();

        if (r < 2) {
            if (tid < 80) {
                __half2 h = __floats2half2_rn(ocum[tid * 2], ocum[tid * 2 + 1]);
                ocum_h[tid] = *reinterpret_cast<unsigned int*>(&h);
            }
            __syncthreads();
        }
    }
}

// ---------------- launch ----------------
extern "C" void kernel_launch(void* const* d_in, const int* in_sizes, int n_in,
                              void* d_out, int out_size) {
    const float* x = (const float*)d_in[0];   // inputs [B, I, Din]
    const float* W = (const float*)d_in[1];   // W      [N, I, D, Din]
    if (n_in >= 2 && in_sizes[0] == N_ * I_ * D_ * K_) {
        const float* t = x; x = W; W = t;
    }
    float* out = (float*)d_out;

    k_uhat<<<I_ / 4, 320>>>(x, W);
    k_route<<<B_, RTH>>>(out);
}

// round 11
// speedup vs baseline: 1.7679x; 1.1635x over previous
#include <cuda_runtime.h>
#include <cuda_fp16.h>
#include <cstdint>

#define B_ 256
#define I_ 1152
#define N_ 10
#define D_ 16
#define K_ 8

// u_hat scratch, layout [b][n][i][d], fp16 = 94 MB (L2-resident)
__device__ __half g_uhat[(size_t)B_ * N_ * I_ * D_];

// ---------------- helpers ----------------
__device__ __forceinline__ unsigned long long pack2(float a, float b) {
    unsigned long long r;
    asm("mov.b64 %0, {%1, %2};" : "=l"(r) : "f"(a), "f"(b));
    return r;
}
__device__ __forceinline__ unsigned long long fma2(unsigned long long a,
                                                   unsigned long long b,
                                                   unsigned long long c) {
    unsigned long long r;
    asm("fma.rn.f32x2 %0, %1, %2, %3;" : "=l"(r) : "l"(a), "l"(b), "l"(c));
    return r;
}
__device__ __forceinline__ unsigned int cvt2h(unsigned long long v) {
    float lo, hi;
    asm("mov.b64 {%0, %1}, %2;" : "=f"(lo), "=f"(hi) : "l"(v));
    __half2 h = __floats2half2_rn(lo, hi);
    return *reinterpret_cast<unsigned int*>(&h);
}

// ---------------- kernel 1: u_hat = einsum('nidk,bik->bnid') fp16 -------------
// Grid 288 (4-i group, all 256 b). 320 threads = (bq 4) x (iloc 4, n 10, dh 2).
// x staged ONCE for all 256 b as (x,x) u64 (64 KB) -> broadcast LDS.64.
// W in regs: 32 u64 d-pairs; each LDS.64 feeds 4 FFMA2; output = 1 STG.128.
__global__ __launch_bounds__(320, 2) void k_uhat(const float* __restrict__ x,
                                                 const float* __restrict__ W) {
    __shared__ unsigned long long sx[256 * 32];  // 64 KB: [bl][iloc*8+k]
    const int tid = threadIdx.x;
    const int i0 = blockIdx.x * 4;

    const int bq   = tid / 80;
    const int t    = tid - bq * 80;
    const int dh   = t & 1;
    const int n    = (t >> 1) % 10;
    const int iloc = t / 20;                     // 0..3

    // W regs: w2[k][p] = (W[d0+2p,k], W[d0+2p+1,k]), d0 = dh*8
    unsigned long long w2[8][4];
    {
        float wv[8][8];
        const float* wp = W + (((size_t)n * I_ + i0 + iloc) * D_ + dh * 8) * K_;
#pragma unroll
        for (int d = 0; d < 8; d++) {
            float4 a = *(const float4*)(wp + d * 8);
            float4 c = *(const float4*)(wp + d * 8 + 4);
            wv[d][0] = a.x; wv[d][1] = a.y; wv[d][2] = a.z; wv[d][3] = a.w;
            wv[d][4] = c.x; wv[d][5] = c.y; wv[d][6] = c.z; wv[d][7] = c.w;
        }
#pragma unroll
        for (int k = 0; k < 8; k++)
#pragma unroll
            for (int p = 0; p < 4; p++)
                w2[k][p] = pack2(wv[2 * p][k], wv[2 * p + 1][k]);
    }

    // stage x for ALL 256 b (coalesced), duplicate into u64 lanes
    for (int idx = tid; idx < 8192; idx += 320) {
        int bl = idx >> 5, rem = idx & 31;
        float v = x[(size_t)bl * (I_ * K_) + i0 * K_ + rem];
        sx[idx] = pack2(v, v);
    }
    __syncthreads();

    const int b0 = bq * 64;
#pragma unroll 2
    for (int j = 0; j < 64; j++) {
        const int bl = b0 + j;
        const unsigned long long* xr = sx + bl * 32 + iloc * 8;
        unsigned long long a0 = 0ull, a1 = 0ull, a2 = 0ull, a3 = 0ull;
#pragma unroll
        for (int k = 0; k < 8; k++) {
            unsigned long long xx = xr[k];
            a0 = fma2(w2[k][0], xx, a0);
            a1 = fma2(w2[k][1], xx, a1);
            a2 = fma2(w2[k][2], xx, a2);
            a3 = fma2(w2[k][3], xx, a3);
        }
        uint4 r;
        r.x = cvt2h(a0); r.y = cvt2h(a1); r.z = cvt2h(a2); r.w = cvt2h(a3);
        *(uint4*)(g_uhat + (((size_t)bl * N_ + n) * I_ + i0 + iloc) * D_ + dh * 8) = r;
    }
}

// ---------------- kernel 2: routing, one 512-thread CTA per b -----------------
#define RTH 512
#define CSTRIDE 1160

__global__ __launch_bounds__(RTH, 2) void k_route(float* __restrict__ out) {
    __shared__ __align__(16) float cbuf[10 * CSTRIDE];   // 46.4 KB, whole I
    __shared__ __align__(16) float sPart[16 * 80];
    __shared__ __align__(16) float stot[160];
    __shared__ __align__(16) float ocum[160];
    __shared__ __align__(16) unsigned int ocum_h[80];    // ocum as half2

    const int tid = threadIdx.x;
    const int b = blockIdx.x;
    const __half* ub = g_uhat + (size_t)b * N_ * I_ * D_;

    const int w = tid >> 5, lane = tid & 31;
    const int il = lane >> 2, dq = lane & 3;
    const int nh = w & 1, wg = w >> 1;
    const int nbase = nh * 5;

#pragma unroll 1
    for (int r = 0; r < 3; r++) {
        // ---- sweep A over ALL I: softmax coefficients (r >= 1) ----
        if (r > 0) {
#pragma unroll 1
            for (int i = tid; i < I_; i += RTH) {
                float lg[10];
#pragma unroll 2
                for (int n = 0; n < 10; n++) {
                    const uint4* p = (const uint4*)(ub + ((size_t)n * I_ + i) * D_);
                    uint4 v0 = p[0], v1 = p[1];
                    uint4 o0 = ((const uint4*)ocum_h)[n * 2];
                    uint4 o1 = ((const uint4*)ocum_h)[n * 2 + 1];
                    __half2 acc = __float2half2_rn(0.0f);
                    acc = __hfma2(*(const __half2*)&v0.x, *(const __half2*)&o0.x, acc);
                    acc = __hfma2(*(const __half2*)&v0.y, *(const __half2*)&o0.y, acc);
                    acc = __hfma2(*(const __half2*)&v0.z, *(const __half2*)&o0.z, acc);
                    acc = __hfma2(*(const __half2*)&v0.w, *(const __half2*)&o0.w, acc);
                    acc = __hfma2(*(const __half2*)&v1.x, *(const __half2*)&o1.x, acc);
                    acc = __hfma2(*(const __half2*)&v1.y, *(const __half2*)&o1.y, acc);
                    acc = __hfma2(*(const __half2*)&v1.z, *(const __half2*)&o1.z, acc);
                    acc = __hfma2(*(const __half2*)&v1.w, *(const __half2*)&o1.w, acc);
                    float2 fa = __half22float2(acc);
                    lg[n] = fa.x + fa.y;
                }
                float m = lg[0];
#pragma unroll
                for (int n = 1; n < 10; n++) m = fmaxf(m, lg[n]);
                float sum = 0.0f;
#pragma unroll
                for (int n = 0; n < 10; n++) { lg[n] = __expf(lg[n] - m); sum += lg[n]; }
                float inv = __fdividef(1.0f, sum);
#pragma unroll
                for (int n = 0; n < 10; n++) cbuf[n * CSTRIDE + i] = lg[n] * inv;
            }
            __syncthreads();
        }

        // ---- sweep B over ALL I: weighted accumulation, 5 n per warp ----
        float sp[5][4];
#pragma unroll
        for (int n = 0; n < 5; n++)
#pragma unroll
            for (int q = 0; q < 4; q++) sp[n][q] = 0.0f;

#pragma unroll 3
        for (int round = 0; round < 18; round++) {
            const int i = round * 64 + wg * 8 + il;
            const __half* ubase = ub + ((size_t)nbase * I_ + i) * D_ + dq * 4;
#pragma unroll
            for (int n = 0; n < 5; n++) {
                uint2 v = *(const uint2*)(ubase + (size_t)n * (I_ * D_));
                float2 f0 = __half22float2(*(const __half2*)&v.x);
                float2 f1 = __half22float2(*(const __half2*)&v.y);
                float cv = (r == 0) ? 0.1f : cbuf[(nbase + n) * CSTRIDE + i];
                sp[n][0] += cv * f0.x;
                sp[n][1] += cv * f0.y;
                sp[n][2] += cv * f1.x;
                sp[n][3] += cv * f1.y;
            }
        }

        // ---- reduce sp over il lanes within warp ----
#pragma unroll
        for (int ofs = 4; ofs <= 16; ofs <<= 1)
#pragma unroll
            for (int n = 0; n < 5; n++)
#pragma unroll
                for (int q = 0; q < 4; q++)
                    sp[n][q] += __shfl_xor_sync(0xffffffffu, sp[n][q], ofs);

        if (il == 0) {
#pragma unroll
            for (int n = 0; n < 5; n++)
                *(float4*)&sPart[w * 80 + n * 16 + dq * 4] =
                    make_float4(sp[n][0], sp[n][1], sp[n][2], sp[n][3]);
        }
        __syncthreads();   // also guards cbuf reuse by next iteration's sweep A

        if (tid < 160) {
            const int n = tid >> 4;
            const int nh2 = (n >= 5);
            const int col = (n - nh2 * 5) * 16 + (tid & 15);
            float s = 0.0f;
#pragma unroll
            for (int j = 0; j < 8; j++) s += sPart[(j * 2 + nh2) * 80 + col];
            stot[tid] = s;
        }
        __syncthreads();

        if (tid < 160) {
            const int n = tid >> 4;
            float ns = 0.0f;
#pragma unroll
            for (int j = 0; j < 16; j++) {
                float tv = stot[n * 16 + j];
                ns += tv * tv;
            }
            float f = sqrtf(ns) / (1.0f + ns);
            float val = stot[tid] * f;
            if (r < 2) ocum[tid] = (r == 0) ? val : ocum[tid] + val;
            else       out[b * 160 + tid] = val;
        }
        __syncthreads();

        if (r < 2) {
            if (tid < 80) {
                __half2 h = __floats2half2_rn(ocum[tid * 2], ocum[tid * 2 + 1]);
                ocum_h[tid] = *reinterpret_cast<unsigned int*>(&h);
            }
            __syncthreads();
        }
    }
}

// ---------------- launch ----------------
extern "C" void kernel_launch(void* const* d_in, const int* in_sizes, int n_in,
                              void* d_out, int out_size) {
    const float* x = (const float*)d_in[0];   // inputs [B, I, Din]
    const float* W = (const float*)d_in[1];   // W      [N, I, D, Din]
    if (n_in >= 2 && in_sizes[0] == N_ * I_ * D_ * K_) {
        const float* t = x; x = W; W = t;
    }
    float* out = (float*)d_out;

    k_uhat<<<I_ / 4, 320>>>(x, W);
    k_route<<<B_, RTH>>>(out);
}